// round 10
// baseline (speedup 1.0000x reference)
#include <cuda_runtime.h>
#include <cuda_fp16.h>
#include <cstdint>

#define DB 4096   // batch rows
#define DL 4096   // labels
#define DH 1024   // hidden

#define TILE_M 128
#define TILE_N 128
#define KCH 64
#define NCHUNK (DH / KCH)           // 16
#define NTX (DL / TILE_N)           // 32 tiles in N
#define NTILES ((DB / TILE_M) * NTX)  // 1024
#define STAGES 3
#define GRID_P 296                  // 2 CTAs x 148 SMs, persistent

// per-stage smem: A(16K) B(16K) — rows of 64 fp16 = 128B, SW128 swizzle
#define ST_A 0
#define ST_B 16384
#define STAGE_BYTES 32768
#define SMEM_DYN (STAGES * STAGE_BYTES)   // 98304 -> 2 CTAs/SM

// ---------------- scratch (static device arrays: allowed) ----------------
__device__ __half g_x[(size_t)DB * DH];
__device__ __half g_w[(size_t)DL * DH];
__device__ float g_diag[DL];

// ---------------- helpers ----------------
__device__ __forceinline__ uint32_t smem_u32(const void* p) {
    uint32_t a;
    asm("{ .reg .u64 t; cvta.to.shared.u64 t, %1; cvt.u32.u64 %0, t; }" : "=r"(a) : "l"(p));
    return a;
}
__device__ __forceinline__ uint32_t swz(uint32_t b) {   // SW128: 16B chunk ^= row%8
    return b ^ ((b >> 3) & 0x70);
}
__device__ __forceinline__ void cp16(uint32_t dst, const void* gsrc) {
    asm volatile("cp.async.cg.shared.global [%0], [%1], 16;" :: "r"(dst), "l"(gsrc));
}
__device__ __forceinline__ void cp_commit() {
    asm volatile("cp.async.commit_group;");
}
__device__ __forceinline__ void cp_wait1() {
    asm volatile("cp.async.wait_group 1;");
}
__device__ __forceinline__ void ldm_x4(uint32_t addr, uint32_t* r) {
    asm volatile("ldmatrix.sync.aligned.m8n8.x4.shared.b16 {%0,%1,%2,%3}, [%4];"
                 : "=r"(r[0]), "=r"(r[1]), "=r"(r[2]), "=r"(r[3]) : "r"(addr));
}
__device__ __forceinline__ void mma4(float* c, const uint32_t* a, uint32_t b0, uint32_t b1) {
    asm volatile(
        "mma.sync.aligned.m16n8k16.row.col.f32.f16.f16.f32 "
        "{%0,%1,%2,%3},{%4,%5,%6,%7},{%8,%9},{%0,%1,%2,%3};"
        : "+f"(c[0]), "+f"(c[1]), "+f"(c[2]), "+f"(c[3])
        : "r"(a[0]), "r"(a[1]), "r"(a[2]), "r"(a[3]), "r"(b0), "r"(b1));
}

// ---------------- convert kernels ----------------
__global__ void __launch_bounds__(256) k_conv_x(const float* __restrict__ x) {
    size_t i = (size_t)blockIdx.x * blockDim.x + threadIdx.x;  // one float4 each
    float4 v = reinterpret_cast<const float4*>(x)[i];
    ushort4 h;
    h.x = __half_as_ushort(__float2half_rn(v.x));
    h.y = __half_as_ushort(__float2half_rn(v.y));
    h.z = __half_as_ushort(__float2half_rn(v.z));
    h.w = __half_as_ushort(__float2half_rn(v.w));
    reinterpret_cast<ushort4*>(g_x)[i] = h;
}

__global__ void __launch_bounds__(256) k_conv_w_diag(const float* __restrict__ W,
                                                     const float* __restrict__ E,
                                                     const float* __restrict__ b) {
    int j = blockIdx.x;                  // label row
    int t = threadIdx.x;                 // 256 threads, 1 float4 each (1024 cols)
    size_t i4 = (size_t)j * 256 + t;
    float4 w = reinterpret_cast<const float4*>(W)[i4];
    float4 e = reinterpret_cast<const float4*>(E)[i4];
    ushort4 h;
    h.x = __half_as_ushort(__float2half_rn(w.x));
    h.y = __half_as_ushort(__float2half_rn(w.y));
    h.z = __half_as_ushort(__float2half_rn(w.z));
    h.w = __half_as_ushort(__float2half_rn(w.w));
    reinterpret_cast<ushort4*>(g_w)[i4] = h;

    float acc = w.x * e.x + w.y * e.y + w.z * e.z + w.w * e.w;
    #pragma unroll
    for (int o = 16; o > 0; o >>= 1) acc += __shfl_xor_sync(0xFFFFFFFFu, acc, o);
    __shared__ float red[8];
    if ((t & 31) == 0) red[t >> 5] = acc;
    __syncthreads();
    if (t == 0) {
        float s = 0.f;
        #pragma unroll
        for (int k = 0; k < 8; k++) s += red[k];
        g_diag[j] = s + b[j];
    }
}

// ---- persistent GEMM: 128x128 CTA tile, 64x32 warp tile, 3-stage --------
// 296 resident CTAs stream a linearized (tile, chunk) queue; the cp.async
// pipeline never drains across tile boundaries.
__global__ void __launch_bounds__(256, 2) k_gemm(float* __restrict__ out) {
    extern __shared__ char smraw[];
    const uint32_t sb = smem_u32(smraw);
    const int tid = threadIdx.x;
    const int lane = tid & 31;
    const int wid = tid >> 5;
    const int warpM = wid & 1;   // 2 warps in M (64 rows each)
    const int warpN = wid >> 1;  // 4 warps in N (32 cols each)

    const char* gx = (const char*)g_x;
    const char* gw = (const char*)g_w;

    const int nTiles = (NTILES - (int)blockIdx.x + GRID_P - 1) / GRID_P;
    const int totQ = nTiles * NCHUNK;

    // issue work item q: chunk (q%16) of tile (blockIdx + (q/16)*GRID_P)
    auto issueQ = [&](int q) {
        const int t = blockIdx.x + (q >> 4) * GRID_P;
        const int r0 = (t >> 5) * TILE_M;          // t / NTX
        const int c0 = (t & (NTX - 1)) * TILE_N;   // t % NTX
        const int kc = (q & 15) * KCH;
        const uint32_t sst = sb + (q % STAGES) * STAGE_BYTES;
        #pragma unroll
        for (int j = 0; j < 8; j++) {
            const int arr = j >> 2;                        // 0: x(A), 1: w(B)
            const int tt = (j & 3) * 256 + tid;            // 0..1023
            const int row = tt >> 3;                       // 0..127
            const int c16 = tt & 7;                        // 16B chunk in 128B row
            const int rb = (arr == 0) ? r0 : c0;
            const char* gb = (arr == 0) ? gx : gw;
            const char* src = gb + ((size_t)(rb + row) * DH + kc + c16 * 8) * 2;
            const uint32_t dst = sst + arr * 16384 + swz(row * 128 + c16 * 16);
            cp16(dst, src);
        }
    };

    float acc[4][4][4];
    #pragma unroll
    for (int mt = 0; mt < 4; mt++)
        #pragma unroll
        for (int nt = 0; nt < 4; nt++)
            #pragma unroll
            for (int q = 0; q < 4; q++) acc[mt][nt][q] = 0.f;

    issueQ(0); cp_commit();
    issueQ(1); cp_commit();

    const int lrow = lane & 15;
    const int lhalf = (lane >> 4) << 4;

    for (int q = 0; q < totQ; q++) {
        cp_wait1();                      // item q landed (q+1 may be in flight)
        __syncthreads();                 // everyone done reading slot (q+2)%3
        if (q + 2 < totQ) issueQ(q + 2);
        cp_commit();                     // empty group at tail keeps wait_group 1 uniform

        const uint32_t s0 = sb + (q % STAGES) * STAGE_BYTES;
        #pragma unroll
        for (int ks = 0; ks < 4; ks++) {
            const uint32_t lsw = swz((uint32_t)(lrow * 128 + ks * 32 + lhalf));
            const uint32_t abase = s0 + ST_A + warpM * 8192 + lsw;   // 64 rows * 128B
            const uint32_t bbase = s0 + ST_B + warpN * 4096 + lsw;   // 32 rows * 128B

            uint32_t bb[2][4];
            ldm_x4(bbase, bb[0]);
            ldm_x4(bbase + 2048, bb[1]);                 // +16 n-rows

            #pragma unroll
            for (int mt = 0; mt < 4; mt++) {
                uint32_t aa[4];
                ldm_x4(abase + mt * 2048, aa);
                #pragma unroll
                for (int nt = 0; nt < 4; nt++) {
                    const int r = nt >> 1, p = nt & 1;
                    mma4(acc[mt][nt], aa, bb[r][p], bb[r][p + 2]);
                }
            }
        }

        if ((q & 15) == 15) {
            // ---- epilogue for the tile just finished; then reset acc ----
            const int t = blockIdx.x + (q >> 4) * GRID_P;
            const int row0 = (t >> 5) * TILE_M;
            const int col0 = (t & (NTX - 1)) * TILE_N;
            const int gid = lane >> 2;
            const int qid = lane & 3;
            #pragma unroll
            for (int nt = 0; nt < 4; nt++) {
                const int n = col0 + warpN * 32 + nt * 8 + qid * 2;
                const float2 d = *reinterpret_cast<const float2*>(&g_diag[n]);
                #pragma unroll
                for (int mt = 0; mt < 4; mt++) {
                    const int m = row0 + warpM * 64 + mt * 16 + gid;
                    float2 v0, v1;
                    v0.x = acc[mt][nt][0] + d.x;
                    v0.y = acc[mt][nt][1] + d.y;
                    v1.x = acc[mt][nt][2] + d.x;
                    v1.y = acc[mt][nt][3] + d.y;
                    *reinterpret_cast<float2*>(&out[(size_t)m * DL + n]) = v0;
                    *reinterpret_cast<float2*>(&out[(size_t)(m + 8) * DL + n]) = v1;
                    acc[mt][nt][0] = 0.f; acc[mt][nt][1] = 0.f;
                    acc[mt][nt][2] = 0.f; acc[mt][nt][3] = 0.f;
                }
            }
        }
    }
}

// ---------------- host ----------------
extern "C" void kernel_launch(void* const* d_in, const int* in_sizes, int n_in,
                              void* d_out, int out_size) {
    (void)in_sizes; (void)n_in; (void)out_size;
    const float* x = (const float*)d_in[0];
    const float* E = (const float*)d_in[1];
    const float* W = (const float*)d_in[2];
    const float* b = (const float*)d_in[3];
    float* out = (float*)d_out;

    k_conv_x<<<(DB * DH / 4) / 256, 256>>>(x);
    k_conv_w_diag<<<DL, 256>>>(W, E, b);

    cudaFuncSetAttribute(k_gemm, cudaFuncAttributeMaxDynamicSharedMemorySize, SMEM_DYN);

    k_gemm<<<GRID_P, 256, SMEM_DYN>>>(out);
}

// round 12
// speedup vs baseline: 1.0372x; 1.0372x over previous
#include <cuda_runtime.h>
#include <cuda_fp16.h>
#include <cstdint>

#define DB 4096   // batch rows
#define DL 4096   // labels
#define DH 1024   // hidden

#define TILE_M 128
#define TILE_N 128
#define KCH 64
#define NCHUNK (DH / KCH)   // 16
#define STAGES 3

// per-stage smem: A(16K) B(16K) — rows of 64 fp16 = 128B, SW128 swizzle
#define ST_A 0
#define ST_B 16384
#define STAGE_BYTES 32768
#define SMEM_DYN (STAGES * STAGE_BYTES)   // 98304 -> 2 CTAs/SM

// ---------------- scratch (static device arrays: allowed) ----------------
__device__ __half g_x[(size_t)DB * DH];
__device__ __half g_w[(size_t)DL * DH];
__device__ float g_diag[DL];

// ---------------- helpers ----------------
__device__ __forceinline__ uint32_t smem_u32(const void* p) {
    uint32_t a;
    asm("{ .reg .u64 t; cvta.to.shared.u64 t, %1; cvt.u32.u64 %0, t; }" : "=r"(a) : "l"(p));
    return a;
}
__device__ __forceinline__ uint32_t swz(uint32_t b) {   // SW128: 16B chunk ^= row%8
    return b ^ ((b >> 3) & 0x70);
}
__device__ __forceinline__ void cp16(uint32_t dst, const void* gsrc) {
    asm volatile("cp.async.cg.shared.global [%0], [%1], 16;" :: "r"(dst), "l"(gsrc));
}
__device__ __forceinline__ void cp_commit() {
    asm volatile("cp.async.commit_group;");
}
__device__ __forceinline__ void cp_wait1() {
    asm volatile("cp.async.wait_group 1;");
}
__device__ __forceinline__ void ldm_x4(uint32_t addr, uint32_t* r) {
    asm volatile("ldmatrix.sync.aligned.m8n8.x4.shared.b16 {%0,%1,%2,%3}, [%4];"
                 : "=r"(r[0]), "=r"(r[1]), "=r"(r[2]), "=r"(r[3]) : "r"(addr));
}
__device__ __forceinline__ void mma4(float* c, const uint32_t* a, uint32_t b0, uint32_t b1) {
    asm volatile(
        "mma.sync.aligned.m16n8k16.row.col.f32.f16.f16.f32 "
        "{%0,%1,%2,%3},{%4,%5,%6,%7},{%8,%9},{%0,%1,%2,%3};"
        : "+f"(c[0]), "+f"(c[1]), "+f"(c[2]), "+f"(c[3])
        : "r"(a[0]), "r"(a[1]), "r"(a[2]), "r"(a[3]), "r"(b0), "r"(b1));
}

// ---------------- fused convert kernel ----------------
// blocks [0, DL): convert W row + compute diag bias
// blocks [DL, DL + DB*DH/1024): convert x (1024 floats per block)
__global__ void __launch_bounds__(256) k_convert(const float* __restrict__ x,
                                                 const float* __restrict__ W,
                                                 const float* __restrict__ E,
                                                 const float* __restrict__ b) {
    const int t = threadIdx.x;
    if (blockIdx.x < DL) {
        const int j = blockIdx.x;                 // label row
        size_t i4 = (size_t)j * 256 + t;          // one float4 each (1024 cols)
        float4 w = reinterpret_cast<const float4*>(W)[i4];
        float4 e = reinterpret_cast<const float4*>(E)[i4];
        ushort4 h;
        h.x = __half_as_ushort(__float2half_rn(w.x));
        h.y = __half_as_ushort(__float2half_rn(w.y));
        h.z = __half_as_ushort(__float2half_rn(w.z));
        h.w = __half_as_ushort(__float2half_rn(w.w));
        reinterpret_cast<ushort4*>(g_w)[i4] = h;

        float acc = w.x * e.x + w.y * e.y + w.z * e.z + w.w * e.w;
        #pragma unroll
        for (int o = 16; o > 0; o >>= 1) acc += __shfl_xor_sync(0xFFFFFFFFu, acc, o);
        __shared__ float red[8];
        if ((t & 31) == 0) red[t >> 5] = acc;
        __syncthreads();
        if (t == 0) {
            float s = 0.f;
            #pragma unroll
            for (int k = 0; k < 8; k++) s += red[k];
            g_diag[j] = s + b[j];
        }
    } else {
        size_t i = (size_t)(blockIdx.x - DL) * 256 + t;   // one float4 each
        float4 v = reinterpret_cast<const float4*>(x)[i];
        ushort4 h;
        h.x = __half_as_ushort(__float2half_rn(v.x));
        h.y = __half_as_ushort(__float2half_rn(v.y));
        h.z = __half_as_ushort(__float2half_rn(v.z));
        h.w = __half_as_ushort(__float2half_rn(v.w));
        reinterpret_cast<ushort4*>(g_x)[i] = h;
    }
}

// ------- GEMM: 128x128 CTA, 64x32 warp tile, 3-stage, reg double-buffer ----
__global__ void __launch_bounds__(256, 2) k_gemm(float* __restrict__ out) {
    extern __shared__ char smraw[];
    const uint32_t sb = smem_u32(smraw);
    const int tid = threadIdx.x;
    const int lane = tid & 31;
    const int wid = tid >> 5;
    const int warpM = wid & 1;   // 2 warps in M (64 rows each)
    const int warpN = wid >> 1;  // 4 warps in N (32 cols each)
    const int row0 = blockIdx.y * TILE_M;
    const int col0 = blockIdx.x * TILE_N;

    const char* gx = (const char*)g_x;
    const char* gw = (const char*)g_w;

    // ---- async copy of one K-chunk into a stage slot (16K A + 16K B) ----
    auto issue = [&](int chunk) {
        const int kc = chunk * KCH;
        const uint32_t sst = sb + (chunk % STAGES) * STAGE_BYTES;
        #pragma unroll
        for (int j = 0; j < 8; j++) {
            const int arr = j >> 2;                        // 0: x(A), 1: w(B)
            const int t = (j & 3) * 256 + tid;             // 0..1023
            const int row = t >> 3;                        // 0..127
            const int c16 = t & 7;                         // 16B chunk in 128B row
            const int rb = (arr == 0) ? row0 : col0;
            const char* gb = (arr == 0) ? gx : gw;
            const char* src = gb + ((size_t)(rb + row) * DH + kc + c16 * 8) * 2;
            const uint32_t dst = sst + arr * 16384 + swz(row * 128 + c16 * 16);
            cp16(dst, src);
        }
    };

    float acc[4][4][4];
    #pragma unroll
    for (int mt = 0; mt < 4; mt++)
        #pragma unroll
        for (int nt = 0; nt < 4; nt++)
            #pragma unroll
            for (int q = 0; q < 4; q++) acc[mt][nt][q] = 0.f;

    issue(0); cp_commit();
    issue(1); cp_commit();

    const int lrow = lane & 15;
    const int lhalf = (lane >> 4) << 4;

    // per-ks swizzled lane offsets (ks in 0..3)
    uint32_t lsw[4];
    #pragma unroll
    for (int ks = 0; ks < 4; ks++)
        lsw[ks] = swz((uint32_t)(lrow * 128 + ks * 32 + lhalf));

    for (int c = 0; c < NCHUNK; c++) {
        cp_wait1();                      // chunk c landed (c+1 may be in flight)
        __syncthreads();                 // everyone done with slot (c+2)%3
        if (c + 2 < NCHUNK) issue(c + 2);
        cp_commit();                     // empty group at tail keeps wait_group 1 uniform

        const uint32_t s0 = sb + (c % STAGES) * STAGE_BYTES;
        const uint32_t abase = s0 + ST_A + warpM * 8192;   // 64 rows * 128B
        const uint32_t bbase = s0 + ST_B + warpN * 4096;   // 32 rows * 128B

        // ---- register double-buffered ks loop ----
        uint32_t bb[2][2][4];   // [buf][16-row group][frag]
        uint32_t aa[2][4];      // [buf][frag]
        ldm_x4(bbase + lsw[0], bb[0][0]);
        ldm_x4(bbase + lsw[0] + 2048, bb[0][1]);

        #pragma unroll
        for (int ks = 0; ks < 4; ks++) {
            const int cur = ks & 1, nxt = cur ^ 1;
            if (ks < 3) {                          // prefetch next ks B frags
                ldm_x4(bbase + lsw[ks + 1], bb[nxt][0]);
                ldm_x4(bbase + lsw[ks + 1] + 2048, bb[nxt][1]);
            }
            ldm_x4(abase + lsw[ks], aa[0]);        // A frag mt=0
            #pragma unroll
            for (int mt = 0; mt < 4; mt++) {
                const int ac = mt & 1, an = ac ^ 1;
                if (mt < 3) ldm_x4(abase + lsw[ks] + (mt + 1) * 2048, aa[an]);
                #pragma unroll
                for (int nt = 0; nt < 4; nt++) {
                    const int r = nt >> 1, p = nt & 1;
                    mma4(acc[mt][nt], aa[ac], bb[cur][r][p], bb[cur][r][p + 2]);
                }
            }
        }
    }

    // ---- epilogue: add diag bias, store float2 pairs ----
    const int gid = lane >> 2;
    const int qid = lane & 3;
    #pragma unroll
    for (int nt = 0; nt < 4; nt++) {
        const int n = col0 + warpN * 32 + nt * 8 + qid * 2;
        const float2 d = *reinterpret_cast<const float2*>(&g_diag[n]);
        #pragma unroll
        for (int mt = 0; mt < 4; mt++) {
            const int m = row0 + warpM * 64 + mt * 16 + gid;
            float2 v0, v1;
            v0.x = acc[mt][nt][0] + d.x;
            v0.y = acc[mt][nt][1] + d.y;
            v1.x = acc[mt][nt][2] + d.x;
            v1.y = acc[mt][nt][3] + d.y;
            *reinterpret_cast<float2*>(&out[(size_t)m * DL + n]) = v0;
            *reinterpret_cast<float2*>(&out[(size_t)(m + 8) * DL + n]) = v1;
        }
    }
}

// ---------------- host ----------------
extern "C" void kernel_launch(void* const* d_in, const int* in_sizes, int n_in,
                              void* d_out, int out_size) {
    (void)in_sizes; (void)n_in; (void)out_size;
    const float* x = (const float*)d_in[0];
    const float* E = (const float*)d_in[1];
    const float* W = (const float*)d_in[2];
    const float* b = (const float*)d_in[3];
    float* out = (float*)d_out;

    k_convert<<<DL + (DB * DH / 4) / 256, 256>>>(x, W, E, b);

    cudaFuncSetAttribute(k_gemm, cudaFuncAttributeMaxDynamicSharedMemorySize, SMEM_DYN);

    dim3 grid(DL / TILE_N, DB / TILE_M);   // (32, 32)
    k_gemm<<<grid, 256, SMEM_DYN>>>(out);
}

// round 13
// speedup vs baseline: 1.0551x; 1.0172x over previous
#include <cuda_runtime.h>
#include <cuda_fp16.h>
#include <cstdint>

#define DB 4096   // batch rows
#define DL 4096   // labels
#define DH 1024   // hidden

#define TILE_M 128
#define TILE_N 128
#define KCH 64
#define NCHUNK (DH / KCH)   // 16
#define STAGES 3

// per-stage smem: A(16K) B(16K) — rows of 64 fp16 = 128B, SW128 swizzle
#define ST_A 0
#define ST_B 16384
#define STAGE_BYTES 32768
#define SMEM_DYN (STAGES * STAGE_BYTES)   // 98304 -> 2 CTAs/SM

// ---------------- scratch (static device arrays: allowed) ----------------
__device__ __half g_x[(size_t)DB * DH];
__device__ __half g_w[(size_t)DL * DH];
__device__ float g_diag[DL];

// ---------------- helpers ----------------
__device__ __forceinline__ uint32_t smem_u32(const void* p) {
    uint32_t a;
    asm("{ .reg .u64 t; cvta.to.shared.u64 t, %1; cvt.u32.u64 %0, t; }" : "=r"(a) : "l"(p));
    return a;
}
__device__ __forceinline__ uint32_t swz(uint32_t b) {   // SW128: 16B chunk ^= row%8
    return b ^ ((b >> 3) & 0x70);
}
__device__ __forceinline__ void cp16(uint32_t dst, const void* gsrc) {
    asm volatile("cp.async.cg.shared.global [%0], [%1], 16;" :: "r"(dst), "l"(gsrc));
}
__device__ __forceinline__ void cp_commit() {
    asm volatile("cp.async.commit_group;");
}
__device__ __forceinline__ void cp_wait1() {
    asm volatile("cp.async.wait_group 1;");
}
__device__ __forceinline__ void ldm_x4(uint32_t addr, uint32_t* r) {
    asm volatile("ldmatrix.sync.aligned.m8n8.x4.shared.b16 {%0,%1,%2,%3}, [%4];"
                 : "=r"(r[0]), "=r"(r[1]), "=r"(r[2]), "=r"(r[3]) : "r"(addr));
}
__device__ __forceinline__ void mma4(float* c, const uint32_t* a, uint32_t b0, uint32_t b1) {
    asm volatile(
        "mma.sync.aligned.m16n8k16.row.col.f32.f16.f16.f32 "
        "{%0,%1,%2,%3},{%4,%5,%6,%7},{%8,%9},{%0,%1,%2,%3};"
        : "+f"(c[0]), "+f"(c[1]), "+f"(c[2]), "+f"(c[3])
        : "r"(a[0]), "r"(a[1]), "r"(a[2]), "r"(a[3]), "r"(b0), "r"(b1));
}

// ---------------- fused convert kernel ----------------
// blocks [0, DL): convert W row + compute diag bias
// blocks [DL, DL + DB*DH/2048): convert x (2048 floats per block, MLP=2)
__global__ void __launch_bounds__(256) k_convert(const float* __restrict__ x,
                                                 const float* __restrict__ W,
                                                 const float* __restrict__ E,
                                                 const float* __restrict__ b) {
    const int t = threadIdx.x;
    if (blockIdx.x < DL) {
        const int j = blockIdx.x;                 // label row
        size_t i4 = (size_t)j * 256 + t;          // one float4 each (1024 cols)
        float4 w = reinterpret_cast<const float4*>(W)[i4];
        float4 e = reinterpret_cast<const float4*>(E)[i4];
        ushort4 h;
        h.x = __half_as_ushort(__float2half_rn(w.x));
        h.y = __half_as_ushort(__float2half_rn(w.y));
        h.z = __half_as_ushort(__float2half_rn(w.z));
        h.w = __half_as_ushort(__float2half_rn(w.w));
        reinterpret_cast<ushort4*>(g_w)[i4] = h;

        float acc = w.x * e.x + w.y * e.y + w.z * e.z + w.w * e.w;
        #pragma unroll
        for (int o = 16; o > 0; o >>= 1) acc += __shfl_xor_sync(0xFFFFFFFFu, acc, o);
        __shared__ float red[8];
        if ((t & 31) == 0) red[t >> 5] = acc;
        __syncthreads();
        if (t == 0) {
            float s = 0.f;
            #pragma unroll
            for (int k = 0; k < 8; k++) s += red[k];
            g_diag[j] = s + b[j];
        }
    } else {
        size_t i = (size_t)(blockIdx.x - DL) * 512 + t;   // two float4 each
        float4 v0 = reinterpret_cast<const float4*>(x)[i];
        float4 v1 = reinterpret_cast<const float4*>(x)[i + 256];
        ushort4 h0, h1;
        h0.x = __half_as_ushort(__float2half_rn(v0.x));
        h0.y = __half_as_ushort(__float2half_rn(v0.y));
        h0.z = __half_as_ushort(__float2half_rn(v0.z));
        h0.w = __half_as_ushort(__float2half_rn(v0.w));
        h1.x = __half_as_ushort(__float2half_rn(v1.x));
        h1.y = __half_as_ushort(__float2half_rn(v1.y));
        h1.z = __half_as_ushort(__float2half_rn(v1.z));
        h1.w = __half_as_ushort(__float2half_rn(v1.w));
        reinterpret_cast<ushort4*>(g_x)[i] = h0;
        reinterpret_cast<ushort4*>(g_x)[i + 256] = h1;
    }
}

// ------- GEMM: 128x128 CTA, 64x32 warp tile, 3-stage, deep reg pipeline ----
__global__ void __launch_bounds__(256, 2) k_gemm(float* __restrict__ out) {
    extern __shared__ char smraw[];
    const uint32_t sb = smem_u32(smraw);
    const int tid = threadIdx.x;
    const int lane = tid & 31;
    const int wid = tid >> 5;
    const int warpM = wid & 1;   // 2 warps in M (64 rows each)
    const int warpN = wid >> 1;  // 4 warps in N (32 cols each)
    const int row0 = blockIdx.y * TILE_M;
    const int col0 = blockIdx.x * TILE_N;

    // ---- cp.async addressing: j*32 rows keeps row%8, so swizzle is j-invariant
    const int rsub = tid >> 3;                 // 0..31
    const int c16 = tid & 7;                   // 16B chunk within 128B row
    const uint32_t swzbase = swz((uint32_t)(rsub * 128 + c16 * 16));
    const char* baseA = (const char*)g_x + ((size_t)(row0 + rsub) * DH + c16 * 8) * 2;
    const char* baseB = (const char*)g_w + ((size_t)(col0 + rsub) * DH + c16 * 8) * 2;

    auto issue = [&](int chunk) {
        const uint32_t sst = sb + (chunk % STAGES) * STAGE_BYTES;
        const char* pa = baseA + chunk * (KCH * 2);
        const char* pb = baseB + chunk * (KCH * 2);
        #pragma unroll
        for (int j = 0; j < 4; j++)
            cp16(sst + ST_A + swzbase + j * 4096, pa + (size_t)j * (32 * DH * 2));
        #pragma unroll
        for (int j = 0; j < 4; j++)
            cp16(sst + ST_B + swzbase + j * 4096, pb + (size_t)j * (32 * DH * 2));
    };

    float acc[4][4][4];
    #pragma unroll
    for (int mt = 0; mt < 4; mt++)
        #pragma unroll
        for (int nt = 0; nt < 4; nt++)
            #pragma unroll
            for (int q = 0; q < 4; q++) acc[mt][nt][q] = 0.f;

    issue(0); cp_commit();
    issue(1); cp_commit();

    const int lrow = lane & 15;
    const int lhalf = (lane >> 4) << 4;
    uint32_t lsw[4];
    #pragma unroll
    for (int ks = 0; ks < 4; ks++)
        lsw[ks] = swz((uint32_t)(lrow * 128 + ks * 32 + lhalf));

    for (int c = 0; c < NCHUNK; c++) {
        cp_wait1();                      // chunk c landed (c+1 may be in flight)
        __syncthreads();                 // everyone done with slot (c+2)%3
        if (c + 2 < NCHUNK) issue(c + 2);
        cp_commit();                     // empty group at tail keeps wait_group 1 uniform

        const uint32_t s0 = sb + (c % STAGES) * STAGE_BYTES;
        const uint32_t abase = s0 + ST_A + warpM * 8192;   // 64 rows * 128B
        const uint32_t bbase = s0 + ST_B + warpN * 4096;   // 32 rows * 128B

        uint32_t aa[3][4];      // rotating A frags, prefetch distance 2
        uint32_t bb[2][2][4];   // ks-double-buffered B frags, prefetch distance 4
        ldm_x4(bbase + lsw[0], bb[0][0]);
        ldm_x4(bbase + lsw[0] + 2048, bb[0][1]);
        ldm_x4(abase + lsw[0], aa[0]);
        ldm_x4(abase + lsw[0] + 2048, aa[1]);

        #pragma unroll
        for (int u = 0; u < 16; u++) {
            const int ks = u >> 2, mt = u & 3;
            if (u + 2 < 16) {                      // prefetch A frag for u+2
                const int u2 = u + 2;
                ldm_x4(abase + lsw[u2 >> 2] + (u2 & 3) * 2048, aa[u2 % 3]);
            }
            if (mt == 0 && ks < 3) {               // prefetch B frags for ks+1
                ldm_x4(bbase + lsw[ks + 1], bb[(ks + 1) & 1][0]);
                ldm_x4(bbase + lsw[ks + 1] + 2048, bb[(ks + 1) & 1][1]);
            }
            const uint32_t* a = aa[u % 3];
            #pragma unroll
            for (int nt = 0; nt < 4; nt++) {
                const int r = nt >> 1, p = nt & 1;
                mma4(acc[mt][nt], a, bb[ks & 1][r][p], bb[ks & 1][r][p + 2]);
            }
        }
    }

    // ---- epilogue: add diag bias, store float2 pairs ----
    const int gid = lane >> 2;
    const int qid = lane & 3;
    #pragma unroll
    for (int nt = 0; nt < 4; nt++) {
        const int n = col0 + warpN * 32 + nt * 8 + qid * 2;
        const float2 d = *reinterpret_cast<const float2*>(&g_diag[n]);
        #pragma unroll
        for (int mt = 0; mt < 4; mt++) {
            const int m = row0 + warpM * 64 + mt * 16 + gid;
            float2 v0, v1;
            v0.x = acc[mt][nt][0] + d.x;
            v0.y = acc[mt][nt][1] + d.y;
            v1.x = acc[mt][nt][2] + d.x;
            v1.y = acc[mt][nt][3] + d.y;
            *reinterpret_cast<float2*>(&out[(size_t)m * DL + n]) = v0;
            *reinterpret_cast<float2*>(&out[(size_t)(m + 8) * DL + n]) = v1;
        }
    }
}

// ---------------- host ----------------
extern "C" void kernel_launch(void* const* d_in, const int* in_sizes, int n_in,
                              void* d_out, int out_size) {
    (void)in_sizes; (void)n_in; (void)out_size;
    const float* x = (const float*)d_in[0];
    const float* E = (const float*)d_in[1];
    const float* W = (const float*)d_in[2];
    const float* b = (const float*)d_in[3];
    float* out = (float*)d_out;

    k_convert<<<DL + (DB * DH / 4) / 512, 256>>>(x, W, E, b);

    cudaFuncSetAttribute(k_gemm, cudaFuncAttributeMaxDynamicSharedMemorySize, SMEM_DYN);

    dim3 grid(DL / TILE_N, DB / TILE_M);   // (32, 32)
    k_gemm<<<grid, 256, SMEM_DYN>>>(out);
}

// round 14
// speedup vs baseline: 1.1133x; 1.0552x over previous
#include <cuda_runtime.h>
#include <cuda_fp16.h>
#include <cstdint>

#define DB 4096   // batch rows
#define DL 4096   // labels
#define DH 1024   // hidden

#define TILE_M 128
#define TILE_N 128
#define KCH 64
#define NCHUNK (DH / KCH)   // 16
#define STAGES 3

// per-stage smem: A(16K) B(16K) — rows of 64 fp16 = 128B, SW128 swizzle
#define ST_A 0
#define ST_B 16384
#define STAGE_BYTES 32768
#define SMEM_DYN (STAGES * STAGE_BYTES)   // 98304 -> 2 CTAs/SM

// ---------------- scratch (static device arrays: allowed) ----------------
__device__ __half g_x[(size_t)DB * DH];
__device__ __half g_w[(size_t)DL * DH];
__device__ float g_diag[DL];

// ---------------- helpers ----------------
__device__ __forceinline__ uint32_t smem_u32(const void* p) {
    uint32_t a;
    asm("{ .reg .u64 t; cvta.to.shared.u64 t, %1; cvt.u32.u64 %0, t; }" : "=r"(a) : "l"(p));
    return a;
}
__device__ __forceinline__ uint32_t swz(uint32_t b) {   // SW128: 16B chunk ^= row%8
    return b ^ ((b >> 3) & 0x70);
}
__device__ __forceinline__ void cp16(uint32_t dst, const void* gsrc) {
    asm volatile("cp.async.cg.shared.global [%0], [%1], 16;" :: "r"(dst), "l"(gsrc));
}
__device__ __forceinline__ void cp_commit() {
    asm volatile("cp.async.commit_group;");
}
__device__ __forceinline__ void cp_wait0() {
    asm volatile("cp.async.wait_group 0;");
}
__device__ __forceinline__ void ldm_x4(uint32_t addr, uint32_t* r) {
    asm volatile("ldmatrix.sync.aligned.m8n8.x4.shared.b16 {%0,%1,%2,%3}, [%4];"
                 : "=r"(r[0]), "=r"(r[1]), "=r"(r[2]), "=r"(r[3]) : "r"(addr));
}
__device__ __forceinline__ void mma4(float* c, const uint32_t* a, uint32_t b0, uint32_t b1) {
    asm volatile(
        "mma.sync.aligned.m16n8k16.row.col.f32.f16.f16.f32 "
        "{%0,%1,%2,%3},{%4,%5,%6,%7},{%8,%9},{%0,%1,%2,%3};"
        : "+f"(c[0]), "+f"(c[1]), "+f"(c[2]), "+f"(c[3])
        : "r"(a[0]), "r"(a[1]), "r"(a[2]), "r"(a[3]), "r"(b0), "r"(b1));
}

// ---------------- fused convert kernel ----------------
__global__ void __launch_bounds__(256) k_convert(const float* __restrict__ x,
                                                 const float* __restrict__ W,
                                                 const float* __restrict__ E,
                                                 const float* __restrict__ b) {
    const int t = threadIdx.x;
    if (blockIdx.x < DL) {
        const int j = blockIdx.x;                 // label row
        size_t i4 = (size_t)j * 256 + t;          // one float4 each (1024 cols)
        float4 w = reinterpret_cast<const float4*>(W)[i4];
        float4 e = reinterpret_cast<const float4*>(E)[i4];
        ushort4 h;
        h.x = __half_as_ushort(__float2half_rn(w.x));
        h.y = __half_as_ushort(__float2half_rn(w.y));
        h.z = __half_as_ushort(__float2half_rn(w.z));
        h.w = __half_as_ushort(__float2half_rn(w.w));
        reinterpret_cast<ushort4*>(g_w)[i4] = h;

        float acc = w.x * e.x + w.y * e.y + w.z * e.z + w.w * e.w;
        #pragma unroll
        for (int o = 16; o > 0; o >>= 1) acc += __shfl_xor_sync(0xFFFFFFFFu, acc, o);
        __shared__ float red[8];
        if ((t & 31) == 0) red[t >> 5] = acc;
        __syncthreads();
        if (t == 0) {
            float s = 0.f;
            #pragma unroll
            for (int k = 0; k < 8; k++) s += red[k];
            g_diag[j] = s + b[j];
        }
    } else {
        size_t i = (size_t)(blockIdx.x - DL) * 512 + t;   // two float4 each
        float4 v0 = reinterpret_cast<const float4*>(x)[i];
        float4 v1 = reinterpret_cast<const float4*>(x)[i + 256];
        ushort4 h0, h1;
        h0.x = __half_as_ushort(__float2half_rn(v0.x));
        h0.y = __half_as_ushort(__float2half_rn(v0.y));
        h0.z = __half_as_ushort(__float2half_rn(v0.z));
        h0.w = __half_as_ushort(__float2half_rn(v0.w));
        h1.x = __half_as_ushort(__float2half_rn(v1.x));
        h1.y = __half_as_ushort(__float2half_rn(v1.y));
        h1.z = __half_as_ushort(__float2half_rn(v1.z));
        h1.w = __half_as_ushort(__float2half_rn(v1.w));
        reinterpret_cast<ushort4*>(g_x)[i] = h0;
        reinterpret_cast<ushort4*>(g_x)[i + 256] = h1;
    }
}

// -- GEMM: 128x128 CTA, 64x32 warp tile, 3-stage, seamless frag pipeline ----
__global__ void __launch_bounds__(256, 2) k_gemm(float* __restrict__ out) {
    extern __shared__ char smraw[];
    const uint32_t sb = smem_u32(smraw);
    const int tid = threadIdx.x;
    const int lane = tid & 31;
    const int wid = tid >> 5;
    const int warpM = wid & 1;   // 2 warps in M (64 rows each)
    const int warpN = wid >> 1;  // 4 warps in N (32 cols each)
    const int row0 = blockIdx.y * TILE_M;
    const int col0 = blockIdx.x * TILE_N;

    // cp.async addressing: j*32 rows keeps row%8, so swizzle is j-invariant
    const int rsub = tid >> 3;                 // 0..31
    const int c16 = tid & 7;                   // 16B chunk within 128B row
    const uint32_t swzbase = swz((uint32_t)(rsub * 128 + c16 * 16));
    const char* baseA = (const char*)g_x + ((size_t)(row0 + rsub) * DH + c16 * 8) * 2;
    const char* baseB = (const char*)g_w + ((size_t)(col0 + rsub) * DH + c16 * 8) * 2;

    auto issue = [&](int chunk) {
        const uint32_t sst = sb + (chunk % STAGES) * STAGE_BYTES;
        const char* pa = baseA + chunk * (KCH * 2);
        const char* pb = baseB + chunk * (KCH * 2);
        #pragma unroll
        for (int j = 0; j < 4; j++)
            cp16(sst + ST_A + swzbase + j * 4096, pa + (size_t)j * (32 * DH * 2));
        #pragma unroll
        for (int j = 0; j < 4; j++)
            cp16(sst + ST_B + swzbase + j * 4096, pb + (size_t)j * (32 * DH * 2));
    };

    float acc[4][4][4];
    #pragma unroll
    for (int mt = 0; mt < 4; mt++)
        #pragma unroll
        for (int nt = 0; nt < 4; nt++)
            #pragma unroll
            for (int q = 0; q < 4; q++) acc[mt][nt][q] = 0.f;

    issue(0); cp_commit();
    issue(1); cp_commit();

    const int lrow = lane & 15;
    const int lhalf = (lane >> 4) << 4;
    uint32_t lsw[4];
    #pragma unroll
    for (int ks = 0; ks < 4; ks++)
        lsw[ks] = swz((uint32_t)(lrow * 128 + ks * 32 + lhalf));

    uint32_t aa[4][4];      // A frag ring, prefetch distance 3 (16 % 4 == 0: phase-stable)
    uint32_t bb[2][2][4];   // B frags, ks-parity double buffer (4 ks: phase-stable)

    // prologue: slot 0 resident; preload frags for u = 0,1,2 and ks = 0
    cp_wait0();
    __syncthreads();
    {
        const uint32_t a0 = sb + ST_A + warpM * 8192;
        const uint32_t b0 = sb + ST_B + warpN * 4096;
        ldm_x4(a0 + lsw[0], aa[0]);
        ldm_x4(a0 + lsw[0] + 2048, aa[1]);
        ldm_x4(a0 + lsw[0] + 4096, aa[2]);
        ldm_x4(b0 + lsw[0], bb[0][0]);
        ldm_x4(b0 + lsw[0] + 2048, bb[0][1]);
    }

    for (int c = 0; c < NCHUNK; c++) {
        cp_wait0();                      // slots c and c+1 both resident
        __syncthreads();                 // everyone done reading slot (c+2)%3
        if (c + 2 < NCHUNK) { issue(c + 2); cp_commit(); }

        const uint32_t s0 = sb + (c % STAGES) * STAGE_BYTES;
        const uint32_t s1 = sb + ((c + 1) % STAGES) * STAGE_BYTES;
        const uint32_t abase = s0 + ST_A + warpM * 8192;
        const uint32_t bbase = s0 + ST_B + warpN * 4096;
        const uint32_t abase_n = s1 + ST_A + warpM * 8192;   // next chunk (stale junk at c=15; unused)
        const uint32_t bbase_n = s1 + ST_B + warpN * 4096;

        #pragma unroll
        for (int u = 0; u < 16; u++) {
            const int ks = u >> 2, mt = u & 3;
            {   // A prefetch, distance 3 (crosses into next chunk's slot at the seam)
                const int u3 = u + 3;
                if (u3 < 16) ldm_x4(abase + lsw[u3 >> 2] + (u3 & 3) * 2048, aa[u3 & 3]);
                else         ldm_x4(abase_n + lsw[0] + (u3 - 16) * 2048, aa[u3 & 3]);
            }
            if (mt == 0) {   // B prefetch for next ks (or next chunk's ks=0 at the seam)
                if (ks < 3) {
                    ldm_x4(bbase + lsw[ks + 1], bb[(ks + 1) & 1][0]);
                    ldm_x4(bbase + lsw[ks + 1] + 2048, bb[(ks + 1) & 1][1]);
                } else {
                    ldm_x4(bbase_n + lsw[0], bb[0][0]);
                    ldm_x4(bbase_n + lsw[0] + 2048, bb[0][1]);
                }
            }
            const uint32_t* a = aa[u & 3];
            #pragma unroll
            for (int nt = 0; nt < 4; nt++) {
                const int r = nt >> 1, p = nt & 1;
                mma4(acc[mt][nt], a, bb[ks & 1][r][p], bb[ks & 1][r][p + 2]);
            }
        }
    }

    // ---- epilogue: add diag bias, store float2 pairs ----
    const int gid = lane >> 2;
    const int qid = lane & 3;
    #pragma unroll
    for (int nt = 0; nt < 4; nt++) {
        const int n = col0 + warpN * 32 + nt * 8 + qid * 2;
        const float2 d = *reinterpret_cast<const float2*>(&g_diag[n]);
        #pragma unroll
        for (int mt = 0; mt < 4; mt++) {
            const int m = row0 + warpM * 64 + mt * 16 + gid;
            float2 v0, v1;
            v0.x = acc[mt][nt][0] + d.x;
            v0.y = acc[mt][nt][1] + d.y;
            v1.x = acc[mt][nt][2] + d.x;
            v1.y = acc[mt][nt][3] + d.y;
            *reinterpret_cast<float2*>(&out[(size_t)m * DL + n]) = v0;
            *reinterpret_cast<float2*>(&out[(size_t)(m + 8) * DL + n]) = v1;
        }
    }
}

// ---------------- host ----------------
extern "C" void kernel_launch(void* const* d_in, const int* in_sizes, int n_in,
                              void* d_out, int out_size) {
    (void)in_sizes; (void)n_in; (void)out_size;
    const float* x = (const float*)d_in[0];
    const float* E = (const float*)d_in[1];
    const float* W = (const float*)d_in[2];
    const float* b = (const float*)d_in[3];
    float* out = (float*)d_out;

    k_convert<<<DL + (DB * DH / 4) / 512, 256>>>(x, W, E, b);

    cudaFuncSetAttribute(k_gemm, cudaFuncAttributeMaxDynamicSharedMemorySize, SMEM_DYN);

    dim3 grid(DL / TILE_N, DB / TILE_M);   // (32, 32)
    k_gemm<<<grid, 256, SMEM_DYN>>>(out);
}